// round 1
// baseline (speedup 1.0000x reference)
#include <cuda_runtime.h>

#define BB     64
#define CC     256
#define HH     56
#define WW     56
#define HW     3136          // 56*56
#define NROWS  (BB*CC)       // 16384
#define TOPK   38
#define NSEL   (BB*TOPK)     // 2432
#define HWV4   (HW/4)        // 784 float4 per row

__device__ float g_sums[NROWS];
__device__ int   g_amax[NROWS];
__device__ int   g_list[NSEL];

// ---------------------------------------------------------------------------
// K1: warp-per-row. One streaming pass over x: per-row sum + argmax (first-index
// tie-break), and default copy x -> out.
// ---------------------------------------------------------------------------
__global__ __launch_bounds__(256) void k1_reduce_copy(const float* __restrict__ x,
                                                      float* __restrict__ out) {
    const int warp = threadIdx.x >> 5;
    const int lane = threadIdx.x & 31;
    const int row  = blockIdx.x * 8 + warp;

    const float4* __restrict__ xr  = (const float4*)(x   + (size_t)row * HW);
    float4*       __restrict__ orr = (float4*)      (out + (size_t)row * HW);

    float sum  = 0.0f;
    float mval = -3.402823466e38f;
    int   midx = 0;

    for (int i = lane; i < HWV4; i += 32) {
        float4 v = __ldcs(&xr[i]);
        __stcs(&orr[i], v);
        sum += v.x + v.y + v.z + v.w;
        const int p = i << 2;
        if (v.x > mval) { mval = v.x; midx = p;     }
        if (v.y > mval) { mval = v.y; midx = p + 1; }
        if (v.z > mval) { mval = v.z; midx = p + 2; }
        if (v.w > mval) { mval = v.w; midx = p + 3; }
    }

    // warp reduction: sum and (max, first-index)
    #pragma unroll
    for (int off = 16; off > 0; off >>= 1) {
        sum += __shfl_down_sync(0xffffffffu, sum, off);
        float ov = __shfl_down_sync(0xffffffffu, mval, off);
        int   oi = __shfl_down_sync(0xffffffffu, midx, off);
        if (ov > mval || (ov == mval && oi < midx)) { mval = ov; midx = oi; }
    }
    if (lane == 0) {
        g_sums[row] = sum;
        g_amax[row] = midx;
    }
}

// ---------------------------------------------------------------------------
// K2: one block per batch. SE module (pooled -> relu(w1) -> sigmoid(w2) -> M),
// exact top-38 selection by rank, compacted into g_list.
// ---------------------------------------------------------------------------
__global__ __launch_bounds__(256) void k2_se_topk(const float* __restrict__ w1,
                                                  const float* __restrict__ w2) {
    __shared__ float s_pooled[CC];
    __shared__ float s_hidden[16];
    __shared__ float s_M[CC];

    const int b = blockIdx.x;
    const int t = threadIdx.x;

    s_pooled[t] = g_sums[b * CC + t] * (1.0f / (float)HW);
    __syncthreads();

    if (t < 16) {
        float acc = 0.0f;
        const float* __restrict__ w1r = w1 + t * CC;
        #pragma unroll 8
        for (int c = 0; c < CC; c++) acc += s_pooled[c] * w1r[c];
        s_hidden[t] = fmaxf(acc, 0.0f);
    }
    __syncthreads();

    {
        float acc = 0.0f;
        const float* __restrict__ w2r = w2 + t * 16;
        #pragma unroll
        for (int d = 0; d < 16; d++) acc += s_hidden[d] * w2r[d];
        s_M[t] = 1.0f / (1.0f + expf(-acc));
    }
    __syncthreads();

    // rank = #{j : (M[j], -j) > (M[t], -t)} — exactly TOPK threads get rank < TOPK
    const float m = s_M[t];
    int cnt = 0;
    for (int j = 0; j < CC; j++) {
        const float mj = s_M[j];
        cnt += (mj > m) || (mj == m && j < t);
    }
    if (cnt < TOPK) g_list[b * TOPK + cnt] = b * CC + t;
}

// ---------------------------------------------------------------------------
// K3: warp-per-selected-row. Re-read the 2432 selected rows, apply the clipped
// 5x5 zero box around argmax and rescale by lam = HW / (HW - box_area).
// ---------------------------------------------------------------------------
__global__ __launch_bounds__(256) void k3_apply(const float* __restrict__ x,
                                                float* __restrict__ out) {
    const int warp = threadIdx.x >> 5;
    const int lane = threadIdx.x & 31;
    const int sel  = blockIdx.x * 8 + warp;

    const int row  = g_list[sel];
    const int aidx = g_amax[row];
    const int mh = aidx / WW;
    const int mw = aidx % WW;
    const int h1  = max(mh - 2, 0), h2  = min(mh + 2, HH - 1);
    const int w1b = max(mw - 2, 0), w2b = min(mw + 2, WW - 1);
    const int box = (h2 - h1 + 1) * (w2b - w1b + 1);
    const float lam = (float)HW / (float)(HW - box);

    const float4* __restrict__ xr  = (const float4*)(x   + (size_t)row * HW);
    float4*       __restrict__ orr = (float4*)      (out + (size_t)row * HW);

    for (int i = lane; i < HWV4; i += 32) {
        float4 v = __ldg(&xr[i]);
        const int p  = i << 2;
        const int r  = p / WW;
        const int c0 = p % WW;           // WW % 4 == 0: all 4 in same image row
        const bool rin = (r >= h1) && (r <= h2);
        float4 o;
        o.x = (rin && c0     >= w1b && c0     <= w2b) ? 0.0f : v.x * lam;
        o.y = (rin && c0 + 1 >= w1b && c0 + 1 <= w2b) ? 0.0f : v.y * lam;
        o.z = (rin && c0 + 2 >= w1b && c0 + 2 <= w2b) ? 0.0f : v.z * lam;
        o.w = (rin && c0 + 3 >= w1b && c0 + 3 <= w2b) ? 0.0f : v.w * lam;
        orr[i] = o;
    }
}

// ---------------------------------------------------------------------------
extern "C" void kernel_launch(void* const* d_in, const int* in_sizes, int n_in,
                              void* d_out, int out_size) {
    const float* x  = (const float*)d_in[0];
    const float* w1 = (const float*)d_in[1];
    const float* w2 = (const float*)d_in[2];
    float* out = (float*)d_out;

    k1_reduce_copy<<<NROWS / 8, 256>>>(x, out);   // 2048 blocks
    k2_se_topk   <<<BB,        256>>>(w1, w2);    // 64 blocks
    k3_apply     <<<NSEL / 8,  256>>>(x, out);    // 304 blocks
}

// round 2
// speedup vs baseline: 1.0182x; 1.0182x over previous
#include <cuda_runtime.h>

#define BB     64
#define CC     256
#define HH     56
#define WW     56
#define HW     3136          // 56*56
#define NROWS  (BB*CC)       // 16384
#define TOPK   38
#define NSEL   (BB*TOPK)     // 2432
#define HWV4   (HW/4)        // 784 float4 per row
#define MAIN4  768           // 784 = 6*128 + 16

__device__ float g_sums[NROWS];
__device__ int   g_amax[NROWS];
__device__ int   g_list[NSEL];

__device__ __forceinline__ void acc_max(float v, int p, float& mval, int& midx) {
    if (v > mval) { mval = v; midx = p; }
}

// ---------------------------------------------------------------------------
// K1: warp-per-row, unroll-by-4 (4 LDG.128 front-batched). Streaming read of x
// (evict-first), default write-back stores to out (keep in L2 for K3).
// Per-row sum + argmax (first-index tie-break) + copy x -> out.
// ---------------------------------------------------------------------------
__global__ __launch_bounds__(256) void k1_reduce_copy(const float* __restrict__ x,
                                                      float* __restrict__ out) {
    const int warp = threadIdx.x >> 5;
    const int lane = threadIdx.x & 31;
    const int row  = blockIdx.x * 8 + warp;

    const float4* __restrict__ xr  = (const float4*)(x   + (size_t)row * HW);
    float4*       __restrict__ orr = (float4*)      (out + (size_t)row * HW);

    float s0 = 0.f, s1 = 0.f, s2 = 0.f, s3 = 0.f;
    float mval = -3.402823466e38f;
    int   midx = 0;

    #pragma unroll
    for (int base = 0; base < MAIN4; base += 128) {
        const int i0 = base + lane;
        float4 a = __ldcs(&xr[i0]);
        float4 b = __ldcs(&xr[i0 + 32]);
        float4 c = __ldcs(&xr[i0 + 64]);
        float4 d = __ldcs(&xr[i0 + 96]);
        orr[i0]      = a;
        orr[i0 + 32] = b;
        orr[i0 + 64] = c;
        orr[i0 + 96] = d;
        s0 += a.x + a.y + a.z + a.w;
        s1 += b.x + b.y + b.z + b.w;
        s2 += c.x + c.y + c.z + c.w;
        s3 += d.x + d.y + d.z + d.w;
        int p = (i0) << 2;
        acc_max(a.x, p, mval, midx); acc_max(a.y, p + 1, mval, midx);
        acc_max(a.z, p + 2, mval, midx); acc_max(a.w, p + 3, mval, midx);
        p = (i0 + 32) << 2;
        acc_max(b.x, p, mval, midx); acc_max(b.y, p + 1, mval, midx);
        acc_max(b.z, p + 2, mval, midx); acc_max(b.w, p + 3, mval, midx);
        p = (i0 + 64) << 2;
        acc_max(c.x, p, mval, midx); acc_max(c.y, p + 1, mval, midx);
        acc_max(c.z, p + 2, mval, midx); acc_max(c.w, p + 3, mval, midx);
        p = (i0 + 96) << 2;
        acc_max(d.x, p, mval, midx); acc_max(d.y, p + 1, mval, midx);
        acc_max(d.z, p + 2, mval, midx); acc_max(d.w, p + 3, mval, midx);
    }
    // tail: float4 indices 768..783, lanes 0..15
    if (lane < 16) {
        const int i0 = MAIN4 + lane;
        float4 a = __ldcs(&xr[i0]);
        orr[i0] = a;
        s0 += a.x + a.y + a.z + a.w;
        const int p = i0 << 2;
        acc_max(a.x, p, mval, midx); acc_max(a.y, p + 1, mval, midx);
        acc_max(a.z, p + 2, mval, midx); acc_max(a.w, p + 3, mval, midx);
    }

    float sum = (s0 + s1) + (s2 + s3);

    #pragma unroll
    for (int off = 16; off > 0; off >>= 1) {
        sum += __shfl_down_sync(0xffffffffu, sum, off);
        float ov = __shfl_down_sync(0xffffffffu, mval, off);
        int   oi = __shfl_down_sync(0xffffffffu, midx, off);
        if (ov > mval || (ov == mval && oi < midx)) { mval = ov; midx = oi; }
    }
    if (lane == 0) {
        g_sums[row] = sum;
        g_amax[row] = midx;
    }
}

// ---------------------------------------------------------------------------
// K2: one block per batch. SE module + exact rank-based top-38 selection.
// ---------------------------------------------------------------------------
__global__ __launch_bounds__(256) void k2_se_topk(const float* __restrict__ w1,
                                                  const float* __restrict__ w2) {
    __shared__ float s_pooled[CC];
    __shared__ float s_hidden[16];
    __shared__ float s_M[CC];

    const int b = blockIdx.x;
    const int t = threadIdx.x;

    s_pooled[t] = g_sums[b * CC + t] * (1.0f / (float)HW);
    __syncthreads();

    if (t < 16) {
        float acc = 0.0f;
        const float* __restrict__ w1r = w1 + t * CC;
        #pragma unroll 8
        for (int c = 0; c < CC; c++) acc += s_pooled[c] * w1r[c];
        s_hidden[t] = fmaxf(acc, 0.0f);
    }
    __syncthreads();

    {
        float acc = 0.0f;
        const float* __restrict__ w2r = w2 + t * 16;
        #pragma unroll
        for (int d = 0; d < 16; d++) acc += s_hidden[d] * w2r[d];
        s_M[t] = 1.0f / (1.0f + expf(-acc));
    }
    __syncthreads();

    const float m = s_M[t];
    int cnt = 0;
    for (int j = 0; j < CC; j++) {
        const float mj = s_M[j];
        cnt += (mj > m) || (mj == m && j < t);
    }
    if (cnt < TOPK) g_list[b * TOPK + cnt] = b * CC + t;
}

// ---------------------------------------------------------------------------
// K3: warp-per-selected-row. Reads the row back from OUT (hot in L2 from K1's
// write-back stores), applies clipped 5x5 zero box around argmax + rescale.
// ---------------------------------------------------------------------------
__global__ __launch_bounds__(256) void k3_apply(float* __restrict__ out) {
    const int warp = threadIdx.x >> 5;
    const int lane = threadIdx.x & 31;
    const int sel  = blockIdx.x * 8 + warp;

    const int row  = g_list[sel];
    const int aidx = g_amax[row];
    const int mh = aidx / WW;
    const int mw = aidx % WW;
    const int h1  = max(mh - 2, 0), h2  = min(mh + 2, HH - 1);
    const int w1b = max(mw - 2, 0), w2b = min(mw + 2, WW - 1);
    const int box = (h2 - h1 + 1) * (w2b - w1b + 1);
    const float lam = (float)HW / (float)(HW - box);

    float4* __restrict__ orr = (float4*)(out + (size_t)row * HW);

    #pragma unroll
    for (int base = 0; base < MAIN4; base += 128) {
        const int i0 = base + lane;
        float4 v[4];
        v[0] = orr[i0];
        v[1] = orr[i0 + 32];
        v[2] = orr[i0 + 64];
        v[3] = orr[i0 + 96];
        #pragma unroll
        for (int k = 0; k < 4; k++) {
            const int p  = (i0 + 32 * k) << 2;
            const int r  = p / WW;
            const int c0 = p % WW;              // WW % 4 == 0: same image row
            const bool rin = (r >= h1) && (r <= h2);
            float4 o;
            o.x = (rin && c0     >= w1b && c0     <= w2b) ? 0.0f : v[k].x * lam;
            o.y = (rin && c0 + 1 >= w1b && c0 + 1 <= w2b) ? 0.0f : v[k].y * lam;
            o.z = (rin && c0 + 2 >= w1b && c0 + 2 <= w2b) ? 0.0f : v[k].z * lam;
            o.w = (rin && c0 + 3 >= w1b && c0 + 3 <= w2b) ? 0.0f : v[k].w * lam;
            orr[i0 + 32 * k] = o;
        }
    }
    if (lane < 16) {
        const int i0 = MAIN4 + lane;
        float4 v = orr[i0];
        const int p  = i0 << 2;
        const int r  = p / WW;
        const int c0 = p % WW;
        const bool rin = (r >= h1) && (r <= h2);
        float4 o;
        o.x = (rin && c0     >= w1b && c0     <= w2b) ? 0.0f : v.x * lam;
        o.y = (rin && c0 + 1 >= w1b && c0 + 1 <= w2b) ? 0.0f : v.y * lam;
        o.z = (rin && c0 + 2 >= w1b && c0 + 2 <= w2b) ? 0.0f : v.z * lam;
        o.w = (rin && c0 + 3 >= w1b && c0 + 3 <= w2b) ? 0.0f : v.w * lam;
        orr[i0] = o;
    }
}

// ---------------------------------------------------------------------------
extern "C" void kernel_launch(void* const* d_in, const int* in_sizes, int n_in,
                              void* d_out, int out_size) {
    const float* x  = (const float*)d_in[0];
    const float* w1 = (const float*)d_in[1];
    const float* w2 = (const float*)d_in[2];
    float* out = (float*)d_out;

    k1_reduce_copy<<<NROWS / 8, 256>>>(x, out);   // 2048 blocks
    k2_se_topk   <<<BB,        256>>>(w1, w2);    // 64 blocks
    k3_apply     <<<NSEL / 8,  256>>>(out);       // 304 blocks
}

// round 3
// speedup vs baseline: 1.0688x; 1.0497x over previous
#include <cuda_runtime.h>

#define BB     64
#define CC     256
#define HH     56
#define WW     56
#define HW     3136          // 56*56
#define NROWS  (BB*CC)       // 16384
#define TOPK   38
#define NSEL   (BB*TOPK)     // 2432
#define HWV4   (HW/4)        // 784 float4 per row
#define MAIN4  768           // 784 = 6*128 + 16
#define QW     196           // float4s per quarter-row (784/4)

__device__ float g_sums[NROWS];
__device__ int   g_amax[NROWS];
__device__ int   g_list[NSEL];

// Resolve argmax-update against a 4-element quad: strict improvement only,
// first-index tie-break inside the quad.
__device__ __forceinline__ void quad_max(float4 v, int p, float& mval, int& midx) {
    const float m4 = fmaxf(fmaxf(v.x, v.y), fmaxf(v.z, v.w));
    if (m4 > mval) {
        mval = m4;
        midx = p + ((v.x == m4) ? 0 : (v.y == m4) ? 1 : (v.z == m4) ? 2 : 3);
    }
}

// ---------------------------------------------------------------------------
// K1: warp-per-row, unroll-by-4. Streaming ldcs reads of x, streaming stcs
// writes of out. Per-row sum + argmax (first-index tie-break) + copy x -> out.
// ---------------------------------------------------------------------------
__global__ __launch_bounds__(256) void k1_reduce_copy(const float* __restrict__ x,
                                                      float* __restrict__ out) {
    const int warp = threadIdx.x >> 5;
    const int lane = threadIdx.x & 31;
    const int row  = blockIdx.x * 8 + warp;

    const float4* __restrict__ xr  = (const float4*)(x   + (size_t)row * HW);
    float4*       __restrict__ orr = (float4*)      (out + (size_t)row * HW);

    float s0 = 0.f, s1 = 0.f, s2 = 0.f, s3 = 0.f;
    float mval = -3.402823466e38f;
    int   midx = 0;

    #pragma unroll
    for (int base = 0; base < MAIN4; base += 128) {
        const int i0 = base + lane;
        float4 a = __ldcs(&xr[i0]);
        float4 b = __ldcs(&xr[i0 + 32]);
        float4 c = __ldcs(&xr[i0 + 64]);
        float4 d = __ldcs(&xr[i0 + 96]);
        __stcs(&orr[i0],      a);
        __stcs(&orr[i0 + 32], b);
        __stcs(&orr[i0 + 64], c);
        __stcs(&orr[i0 + 96], d);
        s0 += a.x + a.y + a.z + a.w;
        s1 += b.x + b.y + b.z + b.w;
        s2 += c.x + c.y + c.z + c.w;
        s3 += d.x + d.y + d.z + d.w;
        quad_max(a, (i0)       << 2, mval, midx);
        quad_max(b, (i0 + 32)  << 2, mval, midx);
        quad_max(c, (i0 + 64)  << 2, mval, midx);
        quad_max(d, (i0 + 96)  << 2, mval, midx);
    }
    // tail: float4 indices 768..783, lanes 0..15
    if (lane < 16) {
        const int i0 = MAIN4 + lane;
        float4 a = __ldcs(&xr[i0]);
        __stcs(&orr[i0], a);
        s0 += a.x + a.y + a.z + a.w;
        quad_max(a, i0 << 2, mval, midx);
    }

    float sum = (s0 + s1) + (s2 + s3);

    #pragma unroll
    for (int off = 16; off > 0; off >>= 1) {
        sum += __shfl_down_sync(0xffffffffu, sum, off);
        float ov = __shfl_down_sync(0xffffffffu, mval, off);
        int   oi = __shfl_down_sync(0xffffffffu, midx, off);
        if (ov > mval || (ov == mval && oi < midx)) { mval = ov; midx = oi; }
    }
    if (lane == 0) {
        g_sums[row] = sum;
        g_amax[row] = midx;
    }
}

// ---------------------------------------------------------------------------
// K2: one block per batch. SE module + exact rank-based top-38 selection.
// ---------------------------------------------------------------------------
__global__ __launch_bounds__(256) void k2_se_topk(const float* __restrict__ w1,
                                                  const float* __restrict__ w2) {
    __shared__ float s_pooled[CC];
    __shared__ float s_hidden[16];
    __shared__ float s_M[CC];

    const int b = blockIdx.x;
    const int t = threadIdx.x;

    s_pooled[t] = g_sums[b * CC + t] * (1.0f / (float)HW);
    __syncthreads();

    if (t < 16) {
        float acc = 0.0f;
        const float* __restrict__ w1r = w1 + t * CC;
        #pragma unroll 8
        for (int c = 0; c < CC; c++) acc += s_pooled[c] * w1r[c];
        s_hidden[t] = fmaxf(acc, 0.0f);
    }
    __syncthreads();

    {
        float acc = 0.0f;
        const float* __restrict__ w2r = w2 + t * 16;
        #pragma unroll
        for (int d = 0; d < 16; d++) acc += s_hidden[d] * w2r[d];
        s_M[t] = 1.0f / (1.0f + expf(-acc));
    }
    __syncthreads();

    const float m = s_M[t];
    int cnt = 0;
    for (int j = 0; j < CC; j++) {
        const float mj = s_M[j];
        cnt += (mj > m) || (mj == m && j < t);
    }
    if (cnt < TOPK) g_list[b * TOPK + cnt] = b * CC + t;
}

// ---------------------------------------------------------------------------
// K3: 4 warps per selected row (quarter-row per warp) for latency hiding.
// Reads x (streaming), applies clipped 5x5 zero box around argmax + rescale,
// writes out. Grid: NSEL*4 warps = NSEL/2 blocks of 8 warps.
// ---------------------------------------------------------------------------
__global__ __launch_bounds__(256) void k3_apply(const float* __restrict__ x,
                                                float* __restrict__ out) {
    const int warp = threadIdx.x >> 5;
    const int lane = threadIdx.x & 31;
    const int gw   = blockIdx.x * 8 + warp;      // global warp id
    const int sel  = gw >> 2;                     // selected-row index
    const int part = gw & 3;                      // quarter within the row

    const int row  = g_list[sel];
    const int aidx = g_amax[row];
    const int mh = aidx / WW;
    const int mw = aidx % WW;
    const int h1  = max(mh - 2, 0), h2  = min(mh + 2, HH - 1);
    const int w1b = max(mw - 2, 0), w2b = min(mw + 2, WW - 1);
    const int box = (h2 - h1 + 1) * (w2b - w1b + 1);
    const float lam = (float)HW / (float)(HW - box);

    const float4* __restrict__ xr  = (const float4*)(x   + (size_t)row * HW);
    float4*       __restrict__ orr = (float4*)      (out + (size_t)row * HW);

    const int q0 = part * QW;                     // [q0, q0+196)

    // 196 = 6*32 + 4
    #pragma unroll
    for (int it = 0; it < 6; it += 2) {
        const int i0 = q0 + it * 32 + lane;
        float4 a = __ldcs(&xr[i0]);
        float4 b = __ldcs(&xr[i0 + 32]);
        #pragma unroll
        for (int k = 0; k < 2; k++) {
            const float4 v = k ? b : a;
            const int p  = (i0 + 32 * k) << 2;
            const int r  = p / WW;
            const int c0 = p % WW;                // WW % 4 == 0: same image row
            const bool rin = (r >= h1) && (r <= h2);
            float4 o;
            o.x = (rin && c0     >= w1b && c0     <= w2b) ? 0.0f : v.x * lam;
            o.y = (rin && c0 + 1 >= w1b && c0 + 1 <= w2b) ? 0.0f : v.y * lam;
            o.z = (rin && c0 + 2 >= w1b && c0 + 2 <= w2b) ? 0.0f : v.z * lam;
            o.w = (rin && c0 + 3 >= w1b && c0 + 3 <= w2b) ? 0.0f : v.w * lam;
            __stcs(&orr[i0 + 32 * k], o);
        }
    }
    if (lane < 4) {
        const int i0 = q0 + 192 + lane;
        float4 v = __ldcs(&xr[i0]);
        const int p  = i0 << 2;
        const int r  = p / WW;
        const int c0 = p % WW;
        const bool rin = (r >= h1) && (r <= h2);
        float4 o;
        o.x = (rin && c0     >= w1b && c0     <= w2b) ? 0.0f : v.x * lam;
        o.y = (rin && c0 + 1 >= w1b && c0 + 1 <= w2b) ? 0.0f : v.y * lam;
        o.z = (rin && c0 + 2 >= w1b && c0 + 2 <= w2b) ? 0.0f : v.z * lam;
        o.w = (rin && c0 + 3 >= w1b && c0 + 3 <= w2b) ? 0.0f : v.w * lam;
        __stcs(&orr[i0], o);
    }
}

// ---------------------------------------------------------------------------
extern "C" void kernel_launch(void* const* d_in, const int* in_sizes, int n_in,
                              void* d_out, int out_size) {
    const float* x  = (const float*)d_in[0];
    const float* w1 = (const float*)d_in[1];
    const float* w2 = (const float*)d_in[2];
    float* out = (float*)d_out;

    k1_reduce_copy<<<NROWS / 8, 256>>>(x, out);   // 2048 blocks
    k2_se_topk   <<<BB,        256>>>(w1, w2);    // 64 blocks
    k3_apply     <<<NSEL / 2,  256>>>(x, out);    // 1216 blocks, 4 warps/row
}